// round 1
// baseline (speedup 1.0000x reference)
#include <cuda_runtime.h>
#include <cstdint>

#define BATCH 16384
#define H 256
#define OUTD 10
#define IND 784
#define TSTEPS 50

typedef unsigned long long ull;

// -------- device scratch (static allocation per harness rules) --------
__device__ float g_X[BATCH * H];            // rho(data) @ W4.T + b4  (time-invariant)
__device__ float g_W2T[H * H];              // W2 transposed once
__device__ float g_s0[2][BATCH * OUTD];     // ping-pong state
__device__ float g_s1[2][BATCH * H];
__device__ float g_s2[2][BATCH * H];

__device__ __forceinline__ float rho_f(float x) { return fminf(fmaxf(x, 0.0f), 1.0f); }

__device__ __forceinline__ ull pack2(float a, float b) {
    ull r; asm("mov.b64 %0, {%1, %2};" : "=l"(r) : "f"(a), "f"(b)); return r;
}
__device__ __forceinline__ void fma2(ull &d, ull a, ull b) {
    asm("fma.rn.f32x2 %0, %1, %2, %0;" : "+l"(d) : "l"(a), "l"(b));
}
__device__ __forceinline__ float2 unpack2(ull v) {
    float2 f; asm("mov.b64 {%0, %1}, %2;" : "=f"(f.x), "=f"(f.y) : "l"(v)); return f;
}

// ---------------- init: copy state in, transpose W2 ----------------
__global__ void __launch_bounds__(256) init_kernel(
    const float* __restrict__ s0, const float* __restrict__ s1,
    const float* __restrict__ s2, const float* __restrict__ W2)
{
    int idx = blockIdx.x * 256 + threadIdx.x;          // 0 .. BATCH*H/4-1
    ((float4*)g_s1[0])[idx] = ((const float4*)s1)[idx];
    ((float4*)g_s2[0])[idx] = ((const float4*)s2)[idx];
    if (idx < BATCH * OUTD / 4)
        ((float4*)g_s0[0])[idx] = ((const float4*)s0)[idx];
    if (idx < H * H) {
        int k = idx >> 8, j = idx & 255;
        g_W2T[idx] = W2[j * H + k];                    // W2T[k][j] = W2[j][k]
    }
}

// ---------------- prefix: X = rho(data) @ W4.T + b4 ----------------
// NT gemm: X[i][j] = b4[j] + sum_k rho(data[i][k]) * W4[j][k]
__global__ void __launch_bounds__(256) x_kernel(
    const float* __restrict__ data, const float* __restrict__ W4,
    const float* __restrict__ b4)
{
    __shared__ float As[16 * 66];
    __shared__ float Bs[16 * 66];
    const int tid = threadIdx.x;
    const int i0 = blockIdx.x * 64, j0 = blockIdx.y * 64;
    const int tx = tid & 15, ty = tid >> 4;
    const int kk = tid & 15, rr = tid >> 4;

    ull acc[4][2] = {};
    for (int k0 = 0; k0 < IND; k0 += 16) {
#pragma unroll
        for (int q = 0; q < 4; q++) {
            int r = rr + q * 16;
            As[kk * 66 + r] = rho_f(data[(size_t)(i0 + r) * IND + k0 + kk]);
            Bs[kk * 66 + r] = W4[(size_t)(j0 + r) * IND + k0 + kk];
        }
        __syncthreads();
#pragma unroll
        for (int k = 0; k < 16; k++) {
            ull a[4];
#pragma unroll
            for (int i = 0; i < 4; i++) {
                float av = As[k * 66 + ty * 4 + i];
                a[i] = pack2(av, av);
            }
            const ull* wp = (const ull*)(Bs + k * 66 + tx * 4);
            ull w0 = wp[0], w1 = wp[1];
#pragma unroll
            for (int i = 0; i < 4; i++) { fma2(acc[i][0], a[i], w0); fma2(acc[i][1], a[i], w1); }
        }
        __syncthreads();
    }
#pragma unroll
    for (int i = 0; i < 4; i++) {
        size_t row = (size_t)i0 + ty * 4 + i;
        int j = j0 + tx * 4;
        float2 p0 = unpack2(acc[i][0]), p1 = unpack2(acc[i][1]);
        float4 ov = make_float4(p0.x + b4[j], p0.y + b4[j + 1],
                                p1.x + b4[j + 2], p1.y + b4[j + 3]);
        *(float4*)(g_X + row * H + j) = ov;
    }
}

// ---------------- fused step kernel ----------------
#define ROWS 64
#define LD   260          // smem row pitch (floats): float4-aligned, bank-spread
#define BK   32
#define STEP_SMEM_FLOATS (2 * ROWS * LD + BK * H + OUTD * H + ROWS * OUTD)
#define STEP_SMEM_BYTES  (STEP_SMEM_FLOATS * 4)

// acc[i][p] accumulates pair of columns (cbase+2p, cbase+2p+1) for row rbase+i
__device__ __forceinline__ void mm_accum(
    ull (&acc)[4][8], const float* __restrict__ RS,
    const float* __restrict__ Wglob, float* Wc,
    int tid, int rbase, int cbase)
{
#pragma unroll 1
    for (int k0 = 0; k0 < H; k0 += BK) {
        // stage W chunk [BK][H] (coalesced, L2-hot)
#pragma unroll
        for (int q = 0; q < (BK * H) / (256 * 4); q++) {
            int e = (q * 256 + tid) * 4;
            *(float4*)(Wc + e) = *(const float4*)(Wglob + (size_t)k0 * H + e);
        }
        __syncthreads();
#pragma unroll 8
        for (int kk = 0; kk < BK; kk++) {
            ull a[4];
#pragma unroll
            for (int i = 0; i < 4; i++) {
                float av = RS[(rbase + i) * LD + k0 + kk];
                a[i] = pack2(av, av);
            }
            const ull* wr = (const ull*)(Wc + kk * H + cbase);
#pragma unroll
            for (int p = 0; p < 8; p++) {
                ull w = wr[p];
#pragma unroll
                for (int i = 0; i < 4; i++) fma2(acc[i][p], a[i], w);
            }
        }
        __syncthreads();
    }
}

__global__ void __launch_bounds__(256, 1) step_kernel(
    int inbuf, int last, float* __restrict__ dout,
    const float* __restrict__ W2, const float* __restrict__ W0,
    const float* __restrict__ b0, const float* __restrict__ b2)
{
    extern __shared__ float sm[];
    float* RS1 = sm;                       // [ROWS][LD]  rho(s1_old)
    float* RS2 = RS1 + ROWS * LD;          // [ROWS][LD]  rho(s2_old)
    float* Wc  = RS2 + ROWS * LD;          // [BK][H]     weight chunk
    float* W0s = Wc + BK * H;              // [OUTD][H]
    float* RS0 = W0s + OUTD * H;           // [ROWS][OUTD] rho(s0_old)

    const int tid = threadIdx.x;
    const size_t row0 = (size_t)blockIdx.x * ROWS;

    const float* __restrict__ s0in = g_s0[inbuf];
    const float* __restrict__ s1in = g_s1[inbuf];
    const float* __restrict__ s2in = g_s2[inbuf];
    float* s0out = last ? dout : g_s0[inbuf ^ 1];
    float* s1out = last ? (dout + BATCH * OUTD) : g_s1[inbuf ^ 1];
    float* s2out = last ? (dout + BATCH * OUTD + (size_t)BATCH * H) : g_s2[inbuf ^ 1];

    // ---- stage rho(state) tiles ----
#pragma unroll
    for (int q = 0; q < 16; q++) {
        int e = (q * 256 + tid) * 4;
        int r = e >> 8, c = e & 255;
        float4 v = *(const float4*)(s1in + row0 * H + e);
        v.x = rho_f(v.x); v.y = rho_f(v.y); v.z = rho_f(v.z); v.w = rho_f(v.w);
        *(float4*)(RS1 + r * LD + c) = v;
        float4 u = *(const float4*)(s2in + row0 * H + e);
        u.x = rho_f(u.x); u.y = rho_f(u.y); u.z = rho_f(u.z); u.w = rho_f(u.w);
        *(float4*)(RS2 + r * LD + c) = u;
    }
    for (int i = tid; i < ROWS * OUTD; i += 256)
        RS0[i] = rho_f(s0in[row0 * OUTD + i]);
    for (int i = tid; i < OUTD * H; i += 256)
        W0s[i] = W0[i];
    __syncthreads();

    const int tx = tid & 15, ty = tid >> 4;
    const int rbase = ty * 4;        // 16 groups * 4 = 64 rows
    const int cbase = tx * 16;       // 16 groups * 16 = 256 cols

    ull acc[4][8];

    // ================= stage A: s2 update =================
    // n2pre = X + rho(s1) @ W2        (W2[k][j], row-major chunks)
#pragma unroll
    for (int i = 0; i < 4; i++)
#pragma unroll
        for (int p = 0; p < 8; p++) acc[i][p] = 0ULL;
    mm_accum(acc, RS1, W2, Wc, tid, rbase, cbase);

#pragma unroll
    for (int i = 0; i < 4; i++) {
        size_t r = row0 + rbase + i;
#pragma unroll
        for (int q = 0; q < 4; q++) {
            int c = cbase + q * 4;
            float4 xo = *(const float4*)(g_X + r * H + c);
            float4 so = *(const float4*)(s2in + r * H + c);
            float2 p0 = unpack2(acc[i][2 * q]), p1 = unpack2(acc[i][2 * q + 1]);
            float4 ov;
            ov.x = rho_f(0.5f * (so.x + ((so.x >= 0.f && so.x <= 1.f) ? (xo.x + p0.x) : 0.f)));
            ov.y = rho_f(0.5f * (so.y + ((so.y >= 0.f && so.y <= 1.f) ? (xo.y + p0.y) : 0.f)));
            ov.z = rho_f(0.5f * (so.z + ((so.z >= 0.f && so.z <= 1.f) ? (xo.z + p1.x) : 0.f)));
            ov.w = rho_f(0.5f * (so.w + ((so.w >= 0.f && so.w <= 1.f) ? (xo.w + p1.y) : 0.f)));
            *(float4*)(s2out + r * H + c) = ov;
        }
    }

    // ================= stage B: s1 update =================
    // n1pre = b2 + rho(s2) @ W2.T + rho(s0) @ W0   (W2.T via g_W2T)
    {
        const ull* b2p = (const ull*)(b2 + cbase);
#pragma unroll
        for (int p = 0; p < 8; p++) {
            ull bv = b2p[p];
#pragma unroll
            for (int i = 0; i < 4; i++) acc[i][p] = bv;
        }
    }
    mm_accum(acc, RS2, g_W2T, Wc, tid, rbase, cbase);

#pragma unroll
    for (int o = 0; o < OUTD; o++) {
        ull a[4];
#pragma unroll
        for (int i = 0; i < 4; i++) {
            float av = RS0[(rbase + i) * OUTD + o];
            a[i] = pack2(av, av);
        }
        const ull* wr = (const ull*)(W0s + o * H + cbase);
#pragma unroll
        for (int p = 0; p < 8; p++) {
            ull w = wr[p];
#pragma unroll
            for (int i = 0; i < 4; i++) fma2(acc[i][p], a[i], w);
        }
    }

#pragma unroll
    for (int i = 0; i < 4; i++) {
        size_t r = row0 + rbase + i;
#pragma unroll
        for (int q = 0; q < 4; q++) {
            int c = cbase + q * 4;
            float4 so = *(const float4*)(s1in + r * H + c);
            float2 p0 = unpack2(acc[i][2 * q]), p1 = unpack2(acc[i][2 * q + 1]);
            float4 ov;
            ov.x = rho_f(0.5f * (so.x + ((so.x >= 0.f && so.x <= 1.f) ? p0.x : 0.f)));
            ov.y = rho_f(0.5f * (so.y + ((so.y >= 0.f && so.y <= 1.f) ? p0.y : 0.f)));
            ov.z = rho_f(0.5f * (so.z + ((so.z >= 0.f && so.z <= 1.f) ? p1.x : 0.f)));
            ov.w = rho_f(0.5f * (so.w + ((so.w >= 0.f && so.w <= 1.f) ? p1.y : 0.f)));
            *(float4*)(s1out + r * H + c) = ov;
        }
    }

    // ================= s0 update =================
    // n0 = b0 + rho(s1) @ W0.T ; s0' = clip(0.5*(s0 + n0))   (no rhop gate)
    for (int idx = tid; idx < ROWS * OUTD; idx += 256) {
        int o = idx >> 6;          // warp shares o -> W0s reads broadcast
        int r = idx & 63;
        float av = 0.f;
#pragma unroll 8
        for (int k = 0; k < H; k += 4) {
            float4 a = *(const float4*)(RS1 + r * LD + k);
            float4 w = *(const float4*)(W0s + o * H + k);
            av = fmaf(a.x, w.x, fmaf(a.y, w.y, fmaf(a.z, w.z, fmaf(a.w, w.w, av))));
        }
        av += b0[o];
        float s = s0in[(row0 + r) * OUTD + o];
        s0out[(row0 + r) * OUTD + o] = rho_f(0.5f * (s + av));
    }
}

// ---------------- launch ----------------
extern "C" void kernel_launch(void* const* d_in, const int* in_sizes, int n_in,
                              void* d_out, int out_size)
{
    (void)in_sizes; (void)n_in; (void)out_size;
    const float* data = (const float*)d_in[0];
    const float* s0   = (const float*)d_in[1];
    const float* s1   = (const float*)d_in[2];
    const float* s2   = (const float*)d_in[3];
    const float* W0   = (const float*)d_in[4];
    const float* b0   = (const float*)d_in[5];
    const float* W2   = (const float*)d_in[6];
    const float* b2   = (const float*)d_in[7];
    const float* W4   = (const float*)d_in[8];
    const float* b4   = (const float*)d_in[9];
    float* out = (float*)d_out;

    cudaFuncSetAttribute(step_kernel, cudaFuncAttributeMaxDynamicSharedMemorySize,
                         STEP_SMEM_BYTES);

    init_kernel<<<(BATCH * H / 4) / 256, 256>>>(s0, s1, s2, W2);
    x_kernel<<<dim3(BATCH / 64, H / 64), 256>>>(data, W4, b4);
    for (int t = 0; t < TSTEPS; t++) {
        step_kernel<<<BATCH / ROWS, 256, STEP_SMEM_BYTES>>>(
            t & 1, t == TSTEPS - 1, out, W2, W0, b0, b2);
    }
}

// round 2
// speedup vs baseline: 1.9491x; 1.9491x over previous
#include <cuda_runtime.h>
#include <cstdint>

#define BATCH 16384
#define H 256
#define OUTD 10
#define IND 784
#define TSTEPS 50

typedef unsigned long long ull;

// -------- device scratch (static allocation per harness rules) --------
__device__ float g_X[BATCH * H];            // rho(data) @ W4.T + b4  (time-invariant)
__device__ float g_W2T[H * H];              // W2 transposed once
__device__ float g_s0[2][BATCH * OUTD];     // ping-pong state
__device__ float g_s1[2][BATCH * H];
__device__ float g_s2[2][BATCH * H];

__device__ __forceinline__ float rho_f(float x) { return fminf(fmaxf(x, 0.0f), 1.0f); }

__device__ __forceinline__ ull pack2(float a, float b) {
    ull r; asm("mov.b64 %0, {%1, %2};" : "=l"(r) : "f"(a), "f"(b)); return r;
}
__device__ __forceinline__ void fma2(ull &d, ull a, ull b) {
    asm("fma.rn.f32x2 %0, %1, %2, %0;" : "+l"(d) : "l"(a), "l"(b));
}
__device__ __forceinline__ float2 unpack2(ull v) {
    float2 f; asm("mov.b64 {%0, %1}, %2;" : "=f"(f.x), "=f"(f.y) : "l"(v)); return f;
}

// ---------------- init: copy state in, transpose W2 ----------------
__global__ void __launch_bounds__(256) init_kernel(
    const float* __restrict__ s0, const float* __restrict__ s1,
    const float* __restrict__ s2, const float* __restrict__ W2)
{
    int idx = blockIdx.x * 256 + threadIdx.x;          // 0 .. BATCH*H/4-1
    ((float4*)g_s1[0])[idx] = ((const float4*)s1)[idx];
    ((float4*)g_s2[0])[idx] = ((const float4*)s2)[idx];
    if (idx < BATCH * OUTD / 4)
        ((float4*)g_s0[0])[idx] = ((const float4*)s0)[idx];
    if (idx < H * H) {
        int k = idx >> 8, j = idx & 255;
        g_W2T[idx] = W2[j * H + k];                    // W2T[k][j] = W2[j][k]
    }
}

// ---------------- prefix: X = rho(data) @ W4.T + b4 ----------------
// NT gemm: X[i][j] = b4[j] + sum_k rho(data[i][k]) * W4[j][k]
__global__ void __launch_bounds__(256) x_kernel(
    const float* __restrict__ data, const float* __restrict__ W4,
    const float* __restrict__ b4)
{
    __shared__ float As[16 * 66];
    __shared__ float Bs[16 * 66];
    const int tid = threadIdx.x;
    const int i0 = blockIdx.x * 64, j0 = blockIdx.y * 64;
    const int tx = tid & 15, ty = tid >> 4;
    const int kk = tid & 15, rr = tid >> 4;

    ull acc[4][2] = {};
    for (int k0 = 0; k0 < IND; k0 += 16) {
#pragma unroll
        for (int q = 0; q < 4; q++) {
            int r = rr + q * 16;
            As[kk * 66 + r] = rho_f(data[(size_t)(i0 + r) * IND + k0 + kk]);
            Bs[kk * 66 + r] = W4[(size_t)(j0 + r) * IND + k0 + kk];
        }
        __syncthreads();
#pragma unroll
        for (int k = 0; k < 16; k++) {
            ull a[4];
#pragma unroll
            for (int i = 0; i < 4; i++) {
                float av = As[k * 66 + ty * 4 + i];
                a[i] = pack2(av, av);
            }
            // interleaved: thread tx handles col pairs 2*tx and 2*tx+32
            const ull* wp0 = (const ull*)(Bs + k * 66 + tx * 2);
            const ull* wp1 = (const ull*)(Bs + k * 66 + 32 + tx * 2);
            ull w0 = *wp0, w1 = *wp1;
#pragma unroll
            for (int i = 0; i < 4; i++) { fma2(acc[i][0], a[i], w0); fma2(acc[i][1], a[i], w1); }
        }
        __syncthreads();
    }
#pragma unroll
    for (int i = 0; i < 4; i++) {
        size_t row = (size_t)i0 + ty * 4 + i;
        float2 p0 = unpack2(acc[i][0]), p1 = unpack2(acc[i][1]);
        int j0a = j0 + tx * 2, j0b = j0 + 32 + tx * 2;
        *(float2*)(g_X + row * H + j0a) = make_float2(p0.x + b4[j0a], p0.y + b4[j0a + 1]);
        *(float2*)(g_X + row * H + j0b) = make_float2(p1.x + b4[j0b], p1.y + b4[j0b + 1]);
    }
}

// ---------------- fused step kernel ----------------
#define ROWS 64
#define LD   260          // smem row pitch (floats): float4-aligned, bank-spread
#define BK   32
#define STEP_SMEM_FLOATS (2 * ROWS * LD + BK * H + OUTD * H + ROWS * OUTD)
#define STEP_SMEM_BYTES  (STEP_SMEM_FLOATS * 4)

// acc[i][p] accumulates column pair (2*tx + 32*p) for row rbase+i.
// For fixed p the 16 tx lanes read 16 consecutive 8B chunks -> conflict-free,
// and both ty half-warps read identical addresses -> broadcast merge.
__device__ __forceinline__ void mm_accum(
    ull (&acc)[4][8], const float* __restrict__ RS,
    const float* __restrict__ Wglob, float* Wc,
    int tid, int rbase, int tx)
{
#pragma unroll 1
    for (int k0 = 0; k0 < H; k0 += BK) {
        // stage W chunk [BK][H] (coalesced, L2-hot)
#pragma unroll
        for (int q = 0; q < (BK * H) / (256 * 4); q++) {
            int e = (q * 256 + tid) * 4;
            *(float4*)(Wc + e) = *(const float4*)(Wglob + (size_t)k0 * H + e);
        }
        __syncthreads();
#pragma unroll 8
        for (int kk = 0; kk < BK; kk++) {
            ull a[4];
#pragma unroll
            for (int i = 0; i < 4; i++) {
                float av = RS[(rbase + i) * LD + k0 + kk];
                a[i] = pack2(av, av);
            }
            const ull* wr = (const ull*)(Wc + kk * H + tx * 2);
#pragma unroll
            for (int p = 0; p < 8; p++) {
                ull w = wr[p * 16];          // p*32 floats = p*16 ull
#pragma unroll
                for (int i = 0; i < 4; i++) fma2(acc[i][p], a[i], w);
            }
        }
        __syncthreads();
    }
}

__global__ void __launch_bounds__(256, 1) step_kernel(
    int inbuf, int last, float* __restrict__ dout,
    const float* __restrict__ W2, const float* __restrict__ W0,
    const float* __restrict__ b0, const float* __restrict__ b2)
{
    extern __shared__ float sm[];
    float* RS1 = sm;                       // [ROWS][LD]  rho(s1_old)
    float* RS2 = RS1 + ROWS * LD;          // [ROWS][LD]  rho(s2_old)
    float* Wc  = RS2 + ROWS * LD;          // [BK][H]     weight chunk
    float* W0s = Wc + BK * H;              // [OUTD][H]
    float* RS0 = W0s + OUTD * H;           // [ROWS][OUTD] rho(s0_old)

    const int tid = threadIdx.x;
    const size_t row0 = (size_t)blockIdx.x * ROWS;

    const float* __restrict__ s0in = g_s0[inbuf];
    const float* __restrict__ s1in = g_s1[inbuf];
    const float* __restrict__ s2in = g_s2[inbuf];
    float* s0out = last ? dout : g_s0[inbuf ^ 1];
    float* s1out = last ? (dout + BATCH * OUTD) : g_s1[inbuf ^ 1];
    float* s2out = last ? (dout + BATCH * OUTD + (size_t)BATCH * H) : g_s2[inbuf ^ 1];

    // ---- stage rho(state) tiles ----
#pragma unroll
    for (int q = 0; q < 16; q++) {
        int e = (q * 256 + tid) * 4;
        int r = e >> 8, c = e & 255;
        float4 v = *(const float4*)(s1in + row0 * H + e);
        v.x = rho_f(v.x); v.y = rho_f(v.y); v.z = rho_f(v.z); v.w = rho_f(v.w);
        *(float4*)(RS1 + r * LD + c) = v;
        float4 u = *(const float4*)(s2in + row0 * H + e);
        u.x = rho_f(u.x); u.y = rho_f(u.y); u.z = rho_f(u.z); u.w = rho_f(u.w);
        *(float4*)(RS2 + r * LD + c) = u;
    }
    for (int i = tid; i < ROWS * OUTD; i += 256)
        RS0[i] = rho_f(s0in[row0 * OUTD + i]);
    for (int i = tid; i < OUTD * H; i += 256)
        W0s[i] = W0[i];
    __syncthreads();

    const int tx = tid & 15, ty = tid >> 4;
    const int rbase = ty * 4;        // 16 groups * 4 = 64 rows
    const int c0 = tx * 2;           // col pairs at c0 + 32*p, p=0..7

    ull acc[4][8];

    // ================= stage A: s2 update =================
    // n2pre = X + rho(s1) @ W2        (W2[k][j], row-major chunks)
#pragma unroll
    for (int i = 0; i < 4; i++)
#pragma unroll
        for (int p = 0; p < 8; p++) acc[i][p] = 0ULL;
    mm_accum(acc, RS1, W2, Wc, tid, rbase, tx);

#pragma unroll
    for (int i = 0; i < 4; i++) {
        size_t r = row0 + rbase + i;
#pragma unroll
        for (int p = 0; p < 8; p++) {
            int c = c0 + 32 * p;
            float2 xo = *(const float2*)(g_X + r * H + c);
            float2 so = *(const float2*)(s2in + r * H + c);
            float2 pr = unpack2(acc[i][p]);
            float2 ov;
            ov.x = rho_f(0.5f * (so.x + ((so.x >= 0.f && so.x <= 1.f) ? (xo.x + pr.x) : 0.f)));
            ov.y = rho_f(0.5f * (so.y + ((so.y >= 0.f && so.y <= 1.f) ? (xo.y + pr.y) : 0.f)));
            *(float2*)(s2out + r * H + c) = ov;
        }
    }

    // ================= stage B: s1 update =================
    // n1pre = b2 + rho(s2) @ W2.T + rho(s0) @ W0   (W2.T via g_W2T)
#pragma unroll
    for (int p = 0; p < 8; p++) {
        ull bv = *(const ull*)(b2 + c0 + 32 * p);
#pragma unroll
        for (int i = 0; i < 4; i++) acc[i][p] = bv;
    }
    mm_accum(acc, RS2, g_W2T, Wc, tid, rbase, tx);

#pragma unroll
    for (int o = 0; o < OUTD; o++) {
        ull a[4];
#pragma unroll
        for (int i = 0; i < 4; i++) {
            float av = RS0[(rbase + i) * OUTD + o];
            a[i] = pack2(av, av);
        }
        const ull* wr = (const ull*)(W0s + o * H + c0);
#pragma unroll
        for (int p = 0; p < 8; p++) {
            ull w = wr[p * 16];
#pragma unroll
            for (int i = 0; i < 4; i++) fma2(acc[i][p], a[i], w);
        }
    }

#pragma unroll
    for (int i = 0; i < 4; i++) {
        size_t r = row0 + rbase + i;
#pragma unroll
        for (int p = 0; p < 8; p++) {
            int c = c0 + 32 * p;
            float2 so = *(const float2*)(s1in + r * H + c);
            float2 pr = unpack2(acc[i][p]);
            float2 ov;
            ov.x = rho_f(0.5f * (so.x + ((so.x >= 0.f && so.x <= 1.f) ? pr.x : 0.f)));
            ov.y = rho_f(0.5f * (so.y + ((so.y >= 0.f && so.y <= 1.f) ? pr.y : 0.f)));
            *(float2*)(s1out + r * H + c) = ov;
        }
    }

    // ================= s0 update =================
    // n0 = b0 + rho(s1) @ W0.T ; s0' = clip(0.5*(s0 + n0))   (no rhop gate)
    for (int idx = tid; idx < ROWS * OUTD; idx += 256) {
        int o = idx >> 6;          // warp shares o -> W0s reads broadcast
        int r = idx & 63;
        float av = 0.f;
#pragma unroll 8
        for (int k = 0; k < H; k += 4) {
            float4 a = *(const float4*)(RS1 + r * LD + k);
            float4 w = *(const float4*)(W0s + o * H + k);
            av = fmaf(a.x, w.x, fmaf(a.y, w.y, fmaf(a.z, w.z, fmaf(a.w, w.w, av))));
        }
        av += b0[o];
        float s = s0in[(row0 + r) * OUTD + o];
        s0out[(row0 + r) * OUTD + o] = rho_f(0.5f * (s + av));
    }
}

// ---------------- launch ----------------
extern "C" void kernel_launch(void* const* d_in, const int* in_sizes, int n_in,
                              void* d_out, int out_size)
{
    (void)in_sizes; (void)n_in; (void)out_size;
    const float* data = (const float*)d_in[0];
    const float* s0   = (const float*)d_in[1];
    const float* s1   = (const float*)d_in[2];
    const float* s2   = (const float*)d_in[3];
    const float* W0   = (const float*)d_in[4];
    const float* b0   = (const float*)d_in[5];
    const float* W2   = (const float*)d_in[6];
    const float* b2   = (const float*)d_in[7];
    const float* W4   = (const float*)d_in[8];
    const float* b4   = (const float*)d_in[9];
    float* out = (float*)d_out;

    cudaFuncSetAttribute(step_kernel, cudaFuncAttributeMaxDynamicSharedMemorySize,
                         STEP_SMEM_BYTES);

    init_kernel<<<(BATCH * H / 4) / 256, 256>>>(s0, s1, s2, W2);
    x_kernel<<<dim3(BATCH / 64, H / 64), 256>>>(data, W4, b4);
    for (int t = 0; t < TSTEPS; t++) {
        step_kernel<<<BATCH / ROWS, 256, STEP_SMEM_BYTES>>>(
            t & 1, t == TSTEPS - 1, out, W2, W0, b0, b2);
    }
}